// round 1
// baseline (speedup 1.0000x reference)
#include <cuda_runtime.h>
#include <math.h>

#define HIDDEN 768
#define KEY    128
#define INTER  1536
#define BDIM   4
#define SEQ    2048
#define M_TOT  (BDIM*SEQ)        // 8192
#define N1     (2*INTER+KEY)     // 3200

// ---------------- scratch (device globals; no allocation allowed) ----------
__device__ float g_u[(size_t)M_TOT * INTER];           // 50 MB  (later overwritten with u*ctx)
__device__ float g_v[(size_t)M_TOT * INTER];           // 50 MB
__device__ float g_q[(size_t)M_TOT * KEY];             // 4 MB
__device__ float g_k[(size_t)M_TOT * KEY];             // 4 MB
__device__ float g_scores[(size_t)BDIM * SEQ * SEQ];   // 64 MB (scores -> attn in place)

// ---------------- generic 128x128x16 SGEMM core ---------------------------
#define BM 128
#define BN 128
#define BKT 16
#define LDS_PAD 132   // 128 + 4 pad: transpose stores conflict-free

// A: [M][K] row-major. B: BT ? [N][K] : [K][N], row-major.
// 256 threads; each computes 8x8. All dims assumed divisible by tile sizes.
template <int KDIM, bool BT>
__device__ __forceinline__ void gemm_core(const float* __restrict__ A,
                                          const float* __restrict__ B,
                                          int lda, int ldb,
                                          int m0, int n0,
                                          float (&acc)[8][8]) {
    __shared__ float As[BKT][LDS_PAD];
    __shared__ float Bs[BKT][LDS_PAD];
    const int tid = threadIdx.x;
    const int tx = tid & 15;       // 0..15 -> 8 cols each
    const int ty = tid >> 4;       // 0..15 -> 8 rows each

    for (int k0 = 0; k0 < KDIM; k0 += BKT) {
        // load A tile (BM x BKT), transposed into smem
        for (int i = tid; i < BM * BKT / 4; i += 256) {
            const int r  = i >> 2;       // 0..127
            const int c4 = i & 3;        // 0..3
            const float4 va = *reinterpret_cast<const float4*>(
                A + (size_t)(m0 + r) * lda + k0 + c4 * 4);
            As[c4 * 4 + 0][r] = va.x;
            As[c4 * 4 + 1][r] = va.y;
            As[c4 * 4 + 2][r] = va.z;
            As[c4 * 4 + 3][r] = va.w;
        }
        if (BT) {
            // B is [N][K]: load rows along K, store transposed
            for (int i = tid; i < BN * BKT / 4; i += 256) {
                const int r  = i >> 2;
                const int c4 = i & 3;
                const float4 vb = *reinterpret_cast<const float4*>(
                    B + (size_t)(n0 + r) * ldb + k0 + c4 * 4);
                Bs[c4 * 4 + 0][r] = vb.x;
                Bs[c4 * 4 + 1][r] = vb.y;
                Bs[c4 * 4 + 2][r] = vb.z;
                Bs[c4 * 4 + 3][r] = vb.w;
            }
        } else {
            // B is [K][N]
            for (int i = tid; i < BKT * BN / 4; i += 256) {
                const int r  = i >> 5;   // 0..15
                const int c4 = i & 31;   // 0..31
                const float4 vb = *reinterpret_cast<const float4*>(
                    B + (size_t)(k0 + r) * ldb + n0 + c4 * 4);
                *reinterpret_cast<float4*>(&Bs[r][c4 * 4]) = vb;
            }
        }
        __syncthreads();
        #pragma unroll
        for (int kk = 0; kk < BKT; kk++) {
            float a[8], b[8];
            #pragma unroll
            for (int i = 0; i < 8; i++) a[i] = As[kk][ty * 8 + i];
            #pragma unroll
            for (int j = 0; j < 8; j++) b[j] = Bs[kk][tx * 8 + j];
            #pragma unroll
            for (int i = 0; i < 8; i++)
                #pragma unroll
                for (int j = 0; j < 8; j++)
                    acc[i][j] = fmaf(a[i], b[j], acc[i][j]);
        }
        __syncthreads();
    }
}

// ---------------- kernel 1: h = silu(X @ Wi + bi), split to u/v/q/k --------
__global__ __launch_bounds__(256) void k_gemm1(const float* __restrict__ hs,
                                               const float* __restrict__ Wi,
                                               const float* __restrict__ bi,
                                               const float* __restrict__ gamma,
                                               const float* __restrict__ beta) {
    float acc[8][8] = {};
    const int m0 = blockIdx.y * BM;
    const int n0 = blockIdx.x * BN;
    gemm_core<HIDDEN, false>(hs, Wi, HIDDEN, N1, m0, n0, acc);
    const int tx = threadIdx.x & 15, ty = threadIdx.x >> 4;
    #pragma unroll
    for (int i = 0; i < 8; i++) {
        const int m = m0 + ty * 8 + i;
        #pragma unroll
        for (int j = 0; j < 8; j++) {
            const int n = n0 + tx * 8 + j;
            const float x = acc[i][j] + bi[n];
            const float s = x / (1.0f + expf(-x));   // silu
            if (n < INTER) {
                g_u[(size_t)m * INTER + n] = s;
            } else if (n < 2 * INTER) {
                g_v[(size_t)m * INTER + (n - INTER)] = s;
            } else {
                const int c = n - 2 * INTER;
                g_q[(size_t)m * KEY + c] = s * gamma[c]        + beta[c];
                g_k[(size_t)m * KEY + c] = s * gamma[KEY + c]  + beta[KEY + c];
            }
        }
    }
}

// ---------------- kernel 2: scores = q @ k^T / sqrt(KEY) + mask ------------
__global__ __launch_bounds__(256) void k_scores(const int* __restrict__ mask) {
    const int b = blockIdx.z;
    const float* qb = g_q + (size_t)b * SEQ * KEY;
    const float* kb = g_k + (size_t)b * SEQ * KEY;
    float acc[8][8] = {};
    const int m0 = blockIdx.y * BM;
    const int n0 = blockIdx.x * BN;
    gemm_core<KEY, true>(qb, kb, KEY, KEY, m0, n0, acc);
    float* sc = g_scores + (size_t)b * SEQ * SEQ;
    const float inv = 0.08838834764831845f;  // 1/sqrt(128)
    const int tx = threadIdx.x & 15, ty = threadIdx.x >> 4;
    #pragma unroll
    for (int i = 0; i < 8; i++) {
        const int m = m0 + ty * 8 + i;
        #pragma unroll
        for (int j = 0; j < 8; j++) {
            const int n = n0 + tx * 8 + j;
            const float am = (1.0f - (float)mask[b * SEQ + n]) * -1.0e12f;
            sc[(size_t)m * SEQ + n] = acc[i][j] * inv + am;
        }
    }
}

// ---------------- kernel 3: length-scaled softmax (in place) ---------------
__global__ __launch_bounds__(256) void k_softmax() {
    float* sc = g_scores + (size_t)blockIdx.x * SEQ;
    const int tid = threadIdx.x;
    __shared__ float red[256];

    float vals[8];
    int cnt = 0;
    #pragma unroll
    for (int t = 0; t < 8; t++) {
        vals[t] = sc[tid + t * 256];
        cnt += (vals[t] > -1.0e11f) ? 1 : 0;
    }
    red[tid] = (float)cnt;
    __syncthreads();
    for (int s = 128; s > 0; s >>= 1) {
        if (tid < s) red[tid] += red[tid + s];
        __syncthreads();
    }
    const float l = fmaxf(red[0], 1.0f);
    const float scale = logf(l) * (1.0f / logf(512.0f));
    __syncthreads();

    float mx = -INFINITY;
    #pragma unroll
    for (int t = 0; t < 8; t++) {
        vals[t] *= scale;
        mx = fmaxf(mx, vals[t]);
    }
    red[tid] = mx;
    __syncthreads();
    for (int s = 128; s > 0; s >>= 1) {
        if (tid < s) red[tid] = fmaxf(red[tid], red[tid + s]);
        __syncthreads();
    }
    mx = red[0];
    __syncthreads();

    float sum = 0.0f;
    #pragma unroll
    for (int t = 0; t < 8; t++) {
        vals[t] = expf(vals[t] - mx);
        sum += vals[t];
    }
    red[tid] = sum;
    __syncthreads();
    for (int s = 128; s > 0; s >>= 1) {
        if (tid < s) red[tid] += red[tid + s];
        __syncthreads();
    }
    const float invsum = 1.0f / red[0];
    #pragma unroll
    for (int t = 0; t < 8; t++)
        sc[tid + t * 256] = vals[t] * invsum;
}

// ---------------- kernel 4: g = u * (attn @ v), in place into g_u ----------
__global__ __launch_bounds__(256) void k_ctx() {
    const int b = blockIdx.z;
    const float* attn = g_scores + (size_t)b * SEQ * SEQ;
    const float* vb   = g_v + (size_t)b * SEQ * INTER;
    float acc[8][8] = {};
    const int m0 = blockIdx.y * BM;
    const int n0 = blockIdx.x * BN;
    gemm_core<SEQ, false>(attn, vb, SEQ, INTER, m0, n0, acc);
    const int tx = threadIdx.x & 15, ty = threadIdx.x >> 4;
    #pragma unroll
    for (int i = 0; i < 8; i++) {
        const int m = m0 + ty * 8 + i;
        #pragma unroll
        for (int j = 0; j < 8; j++) {
            const int n = n0 + tx * 8 + j;
            const size_t idx = ((size_t)b * SEQ + m) * INTER + n;
            g_u[idx] = g_u[idx] * acc[i][j];
        }
    }
}

// ---------------- kernel 5: out = g @ Wo + bo -----------------------------
__global__ __launch_bounds__(256) void k_out(const float* __restrict__ Wo,
                                             const float* __restrict__ bo,
                                             float* __restrict__ out) {
    float acc[8][8] = {};
    const int m0 = blockIdx.y * BM;
    const int n0 = blockIdx.x * BN;
    gemm_core<INTER, false>(g_u, Wo, INTER, HIDDEN, m0, n0, acc);
    const int tx = threadIdx.x & 15, ty = threadIdx.x >> 4;
    #pragma unroll
    for (int i = 0; i < 8; i++) {
        const int m = m0 + ty * 8 + i;
        #pragma unroll
        for (int j = 0; j < 8; j++) {
            const int n = n0 + tx * 8 + j;
            out[(size_t)m * HIDDEN + n] = acc[i][j] + bo[n];
        }
    }
}

// ---------------- launch ---------------------------------------------------
extern "C" void kernel_launch(void* const* d_in, const int* in_sizes, int n_in,
                              void* d_out, int out_size) {
    const float* hs    = (const float*)d_in[0];
    const int*   mask  = (const int*)  d_in[1];
    // d_in[2] = position_ids (unused by reference math)
    const float* Wi    = (const float*)d_in[3];
    const float* bi    = (const float*)d_in[4];
    const float* gamma = (const float*)d_in[5];
    const float* beta  = (const float*)d_in[6];
    const float* Wo    = (const float*)d_in[7];
    const float* bo    = (const float*)d_in[8];
    float* out = (float*)d_out;

    dim3 blk(256);
    k_gemm1  <<<dim3(N1 / BN, M_TOT / BM), blk>>>(hs, Wi, bi, gamma, beta);
    k_scores <<<dim3(SEQ / BN, SEQ / BM, BDIM), blk>>>(mask);
    k_softmax<<<dim3(M_TOT), blk>>>();
    k_ctx    <<<dim3(INTER / BN, SEQ / BM, BDIM), blk>>>();
    k_out    <<<dim3(HIDDEN / BN, M_TOT / BM), blk>>>(Wo, bo, out);
}

// round 2
// speedup vs baseline: 3.0580x; 3.0580x over previous
#include <cuda_runtime.h>
#include <math.h>
#include <stdint.h>

#define HIDDEN 768
#define KEY    128
#define INTER  1536
#define BDIM   4
#define SEQ    2048
#define M_TOT  (BDIM*SEQ)        // 8192
#define N1     (2*INTER+KEY)     // 3200

#define BM 128
#define BN 128
#define BK 16
#define A_LD 20      // As[BM][A_LD]: frag loads conflict-free (20r+c distinct mod 32)
#define B_LD 136     // Bs[BK][B_LD]: frag loads conflict-free (8k+n distinct mod 32)

// ---------------- scratch (device globals; no allocation allowed) ----------
__device__ float g_u[(size_t)M_TOT * INTER];           // u, later u*ctx
__device__ float g_v[(size_t)M_TOT * INTER];
__device__ float g_q[(size_t)M_TOT * KEY];
__device__ float g_k[(size_t)M_TOT * KEY];
__device__ float g_scores[(size_t)BDIM * SEQ * SEQ];   // scores -> attn in place

// ---------------- tf32 helpers ---------------------------------------------
__device__ __forceinline__ float to_tf32(float x) {
    float r;
    asm("cvt.rna.tf32.f32 %0, %1;" : "=f"(r) : "f"(x));
    return r;
}

__device__ __forceinline__ void mma_tf32(float (&c)[4], const uint32_t (&a)[4],
                                         const uint32_t (&b)[2]) {
    asm volatile(
        "mma.sync.aligned.m16n8k8.row.col.f32.tf32.tf32.f32 "
        "{%0,%1,%2,%3}, {%4,%5,%6,%7}, {%8,%9}, {%0,%1,%2,%3};"
        : "+f"(c[0]), "+f"(c[1]), "+f"(c[2]), "+f"(c[3])
        : "r"(a[0]), "r"(a[1]), "r"(a[2]), "r"(a[3]), "r"(b[0]), "r"(b[1]));
}

// ---------------- tf32 tensor-core GEMM core --------------------------------
// 256 threads = 8 warps in 2x4; warp tile 64x32; block tile 128x128.
// A: [M][K] row-major. B: BT ? [N][K] : [K][N], row-major.
// acc[mi][nj][e]: mi = 4 m-tiles of 16, nj = 4 n-tiles of 8, e = c0..c3.
template <int KDIM, bool BT>
__device__ __forceinline__ void gemm_tf32(const float* __restrict__ A,
                                          const float* __restrict__ B,
                                          int lda, int ldb,
                                          int m0, int n0,
                                          float (&acc)[4][4][4]) {
    __shared__ float As[BM][A_LD];
    __shared__ float Bs[BK][B_LD];
    const int tid  = threadIdx.x;
    const int lane = tid & 31;
    const int warp = tid >> 5;
    const int wr   = warp >> 2;   // 0..1  -> m offset 64
    const int wc   = warp & 3;    // 0..3  -> n offset 32
    const int gp   = lane >> 2;   // 0..7
    const int tg   = lane & 3;    // 0..3

    for (int k0 = 0; k0 < KDIM; k0 += BK) {
        // --- stage A tile (BM x BK), row-major, tf32-converted ---
        #pragma unroll
        for (int t = 0; t < 2; t++) {
            const int i  = tid + t * 256;
            const int r  = i >> 2;
            const int c4 = (i & 3) * 4;
            const float4 v = *reinterpret_cast<const float4*>(
                A + (size_t)(m0 + r) * lda + k0 + c4);
            float4 w = make_float4(to_tf32(v.x), to_tf32(v.y),
                                   to_tf32(v.z), to_tf32(v.w));
            *reinterpret_cast<float4*>(&As[r][c4]) = w;
        }
        // --- stage B tile (BK x BN), k-major in smem ---
        if (BT) {
            // B is [N][K]: read along K, transpose into Bs[k][n]
            #pragma unroll
            for (int t = 0; t < 2; t++) {
                const int i  = tid + t * 256;
                const int r  = i >> 2;          // n index 0..127
                const int c4 = (i & 3) * 4;     // k base
                const float4 v = *reinterpret_cast<const float4*>(
                    B + (size_t)(n0 + r) * ldb + k0 + c4);
                Bs[c4 + 0][r] = to_tf32(v.x);
                Bs[c4 + 1][r] = to_tf32(v.y);
                Bs[c4 + 2][r] = to_tf32(v.z);
                Bs[c4 + 3][r] = to_tf32(v.w);
            }
        } else {
            // B is [K][N]: copy rows
            #pragma unroll
            for (int t = 0; t < 2; t++) {
                const int i  = tid + t * 256;
                const int r  = i >> 5;          // k 0..15
                const int c4 = (i & 31) * 4;    // n base
                const float4 v = *reinterpret_cast<const float4*>(
                    B + (size_t)(k0 + r) * ldb + n0 + c4);
                float4 w = make_float4(to_tf32(v.x), to_tf32(v.y),
                                       to_tf32(v.z), to_tf32(v.w));
                *reinterpret_cast<float4*>(&Bs[r][c4]) = w;
            }
        }
        __syncthreads();

        #pragma unroll
        for (int kk = 0; kk < BK; kk += 8) {
            uint32_t a[4][4], b[4][2];
            #pragma unroll
            for (int mi = 0; mi < 4; mi++) {
                const int row = wr * 64 + mi * 16 + gp;
                a[mi][0] = __float_as_uint(As[row    ][kk + tg    ]);
                a[mi][1] = __float_as_uint(As[row + 8][kk + tg    ]);
                a[mi][2] = __float_as_uint(As[row    ][kk + tg + 4]);
                a[mi][3] = __float_as_uint(As[row + 8][kk + tg + 4]);
            }
            #pragma unroll
            for (int nj = 0; nj < 4; nj++) {
                const int col = wc * 32 + nj * 8 + gp;
                b[nj][0] = __float_as_uint(Bs[kk + tg    ][col]);
                b[nj][1] = __float_as_uint(Bs[kk + tg + 4][col]);
            }
            #pragma unroll
            for (int mi = 0; mi < 4; mi++)
                #pragma unroll
                for (int nj = 0; nj < 4; nj++)
                    mma_tf32(acc[mi][nj], a[mi], b[nj]);
        }
        __syncthreads();
    }
}

// Epilogue index helpers: for (mi, nj), reg e in 0..3:
//   m = m0 + wr*64 + mi*16 + gp + (e >= 2 ? 8 : 0)
//   n = n0 + wc*32 + nj*8 + 2*tg + (e & 1)

// ---------------- kernel 1: h = silu(X @ Wi + bi), split u/v/qk ------------
__global__ __launch_bounds__(256) void k_gemm1(const float* __restrict__ hs,
                                               const float* __restrict__ Wi,
                                               const float* __restrict__ bi,
                                               const float* __restrict__ gamma,
                                               const float* __restrict__ beta) {
    float acc[4][4][4] = {};
    const int m0 = blockIdx.y * BM;
    const int n0 = blockIdx.x * BN;
    gemm_tf32<HIDDEN, false>(hs, Wi, HIDDEN, N1, m0, n0, acc);

    const int lane = threadIdx.x & 31, warp = threadIdx.x >> 5;
    const int wr = warp >> 2, wc = warp & 3, gp = lane >> 2, tg = lane & 3;

    #pragma unroll
    for (int mi = 0; mi < 4; mi++)
        #pragma unroll
        for (int nj = 0; nj < 4; nj++)
            #pragma unroll
            for (int e = 0; e < 4; e++) {
                const int m = m0 + wr * 64 + mi * 16 + gp + ((e >> 1) << 3);
                const int n = n0 + wc * 32 + nj * 8 + 2 * tg + (e & 1);
                const float x = acc[mi][nj][e] + bi[n];
                const float s = x / (1.0f + expf(-x));   // silu
                if (n0 < INTER) {
                    g_u[(size_t)m * INTER + n] = s;
                } else if (n0 < 2 * INTER) {
                    g_v[(size_t)m * INTER + (n - INTER)] = s;
                } else {
                    const int c = n - 2 * INTER;
                    g_q[(size_t)m * KEY + c] = s * gamma[c]       + beta[c];
                    g_k[(size_t)m * KEY + c] = s * gamma[KEY + c] + beta[KEY + c];
                }
            }
}

// ---------------- kernel 2: scores = q @ k^T / sqrt(KEY) + mask ------------
__global__ __launch_bounds__(256) void k_scores(const int* __restrict__ mask) {
    const int b = blockIdx.z;
    float acc[4][4][4] = {};
    const int m0 = blockIdx.y * BM;
    const int n0 = blockIdx.x * BN;
    gemm_tf32<KEY, true>(g_q + (size_t)b * SEQ * KEY,
                         g_k + (size_t)b * SEQ * KEY,
                         KEY, KEY, m0, n0, acc);

    float* sc = g_scores + (size_t)b * SEQ * SEQ;
    const float inv = 0.08838834764831845f;  // 1/sqrt(128)
    const int lane = threadIdx.x & 31, warp = threadIdx.x >> 5;
    const int wr = warp >> 2, wc = warp & 3, gp = lane >> 2, tg = lane & 3;

    #pragma unroll
    for (int nj = 0; nj < 4; nj++) {
        const int n = n0 + wc * 32 + nj * 8 + 2 * tg;
        const float am0 = (1.0f - (float)mask[b * SEQ + n    ]) * -1.0e12f;
        const float am1 = (1.0f - (float)mask[b * SEQ + n + 1]) * -1.0e12f;
        #pragma unroll
        for (int mi = 0; mi < 4; mi++) {
            const int m = m0 + wr * 64 + mi * 16 + gp;
            sc[(size_t)m * SEQ + n    ]     = acc[mi][nj][0] * inv + am0;
            sc[(size_t)m * SEQ + n + 1]     = acc[mi][nj][1] * inv + am1;
            sc[(size_t)(m + 8) * SEQ + n    ] = acc[mi][nj][2] * inv + am0;
            sc[(size_t)(m + 8) * SEQ + n + 1] = acc[mi][nj][3] * inv + am1;
        }
    }
}

// ---------------- kernel 3: length-scaled softmax (in place) ---------------
__global__ __launch_bounds__(256) void k_softmax() {
    float* sc = g_scores + (size_t)blockIdx.x * SEQ;
    const int tid = threadIdx.x;
    __shared__ float red[256];

    float vals[8];
    int cnt = 0;
    #pragma unroll
    for (int t = 0; t < 8; t++) {
        vals[t] = sc[tid + t * 256];
        cnt += (vals[t] > -1.0e11f) ? 1 : 0;
    }
    red[tid] = (float)cnt;
    __syncthreads();
    for (int s = 128; s > 0; s >>= 1) {
        if (tid < s) red[tid] += red[tid + s];
        __syncthreads();
    }
    const float l = fmaxf(red[0], 1.0f);
    const float scale = logf(l) * (1.0f / logf(512.0f));
    __syncthreads();

    float mx = -INFINITY;
    #pragma unroll
    for (int t = 0; t < 8; t++) {
        vals[t] *= scale;
        mx = fmaxf(mx, vals[t]);
    }
    red[tid] = mx;
    __syncthreads();
    for (int s = 128; s > 0; s >>= 1) {
        if (tid < s) red[tid] = fmaxf(red[tid], red[tid + s]);
        __syncthreads();
    }
    mx = red[0];
    __syncthreads();

    float sum = 0.0f;
    #pragma unroll
    for (int t = 0; t < 8; t++) {
        vals[t] = expf(vals[t] - mx);
        sum += vals[t];
    }
    red[tid] = sum;
    __syncthreads();
    for (int s = 128; s > 0; s >>= 1) {
        if (tid < s) red[tid] += red[tid + s];
        __syncthreads();
    }
    const float invsum = 1.0f / red[0];
    #pragma unroll
    for (int t = 0; t < 8; t++)
        sc[tid + t * 256] = vals[t] * invsum;
}

// ---------------- kernel 4: g = u * (attn @ v), in place into g_u ----------
__global__ __launch_bounds__(256) void k_ctx() {
    const int b = blockIdx.z;
    float acc[4][4][4] = {};
    const int m0 = blockIdx.y * BM;
    const int n0 = blockIdx.x * BN;
    gemm_tf32<SEQ, false>(g_scores + (size_t)b * SEQ * SEQ,
                          g_v + (size_t)b * SEQ * INTER,
                          SEQ, INTER, m0, n0, acc);

    const int lane = threadIdx.x & 31, warp = threadIdx.x >> 5;
    const int wr = warp >> 2, wc = warp & 3, gp = lane >> 2, tg = lane & 3;

    #pragma unroll
    for (int mi = 0; mi < 4; mi++)
        #pragma unroll
        for (int nj = 0; nj < 4; nj++)
            #pragma unroll
            for (int e = 0; e < 4; e++) {
                const int m = m0 + wr * 64 + mi * 16 + gp + ((e >> 1) << 3);
                const int n = n0 + wc * 32 + nj * 8 + 2 * tg + (e & 1);
                const size_t idx = ((size_t)b * SEQ + m) * INTER + n;
                g_u[idx] = g_u[idx] * acc[mi][nj][e];
            }
}

// ---------------- kernel 5: out = g @ Wo + bo ------------------------------
__global__ __launch_bounds__(256) void k_out(const float* __restrict__ Wo,
                                             const float* __restrict__ bo,
                                             float* __restrict__ out) {
    float acc[4][4][4] = {};
    const int m0 = blockIdx.y * BM;
    const int n0 = blockIdx.x * BN;
    gemm_tf32<INTER, false>(g_u, Wo, INTER, HIDDEN, m0, n0, acc);

    const int lane = threadIdx.x & 31, warp = threadIdx.x >> 5;
    const int wr = warp >> 2, wc = warp & 3, gp = lane >> 2, tg = lane & 3;

    #pragma unroll
    for (int mi = 0; mi < 4; mi++)
        #pragma unroll
        for (int nj = 0; nj < 4; nj++)
            #pragma unroll
            for (int e = 0; e < 4; e++) {
                const int m = m0 + wr * 64 + mi * 16 + gp + ((e >> 1) << 3);
                const int n = n0 + wc * 32 + nj * 8 + 2 * tg + (e & 1);
                out[(size_t)m * HIDDEN + n] = acc[mi][nj][e] + bo[n];
            }
}

// ---------------- launch ---------------------------------------------------
extern "C" void kernel_launch(void* const* d_in, const int* in_sizes, int n_in,
                              void* d_out, int out_size) {
    const float* hs    = (const float*)d_in[0];
    const int*   mask  = (const int*)  d_in[1];
    // d_in[2] = position_ids (unused by reference math)
    const float* Wi    = (const float*)d_in[3];
    const float* bi    = (const float*)d_in[4];
    const float* gamma = (const float*)d_in[5];
    const float* beta  = (const float*)d_in[6];
    const float* Wo    = (const float*)d_in[7];
    const float* bo    = (const float*)d_in[8];
    float* out = (float*)d_out;

    dim3 blk(256);
    k_gemm1  <<<dim3(N1 / BN, M_TOT / BM), blk>>>(hs, Wi, bi, gamma, beta);
    k_scores <<<dim3(SEQ / BN, SEQ / BM, BDIM), blk>>>(mask);
    k_softmax<<<dim3(M_TOT), blk>>>();
    k_ctx    <<<dim3(INTER / BN, SEQ / BM, BDIM), blk>>>();
    k_out    <<<dim3(HIDDEN / BN, M_TOT / BM), blk>>>(Wo, bo, out);
}

// round 3
// speedup vs baseline: 3.5081x; 1.1472x over previous
#include <cuda_runtime.h>
#include <math.h>
#include <stdint.h>

#define HIDDEN 768
#define KEY    128
#define INTER  1536
#define BDIM   4
#define SEQ    2048
#define M_TOT  (BDIM*SEQ)        // 8192
#define N1     (2*INTER+KEY)     // 3200

#define BM 128
#define BN 128
#define BK 16
#define A_LD 20      // As[r][c]: frag LDS conflict-free (20r+c distinct mod 32)
#define B_LD 136     // Bs[k][n]: frag LDS conflict-free (8k+n distinct mod 32)

// ---------------- scratch (device globals; no allocation allowed) ----------
__device__ float g_u[(size_t)M_TOT * INTER];           // u (raw), then tf32(u*ctx)
__device__ float g_v[(size_t)M_TOT * INTER];           // tf32-rounded v
__device__ float g_q[(size_t)M_TOT * KEY];             // tf32-rounded q
__device__ float g_kT[(size_t)BDIM * KEY * SEQ];       // tf32-rounded k, transposed
__device__ float g_scores[(size_t)BDIM * SEQ * SEQ];   // scores -> tf32 attn in place
__device__ float g_hs[(size_t)M_TOT * HIDDEN];         // tf32-rounded hidden_states
__device__ float g_wi[(size_t)HIDDEN * N1];            // tf32-rounded Wi
__device__ float g_wo[(size_t)INTER * HIDDEN];         // tf32-rounded Wo

// ---------------- helpers ---------------------------------------------------
__device__ __forceinline__ float to_tf32(float x) {
    float r;
    asm("cvt.rna.tf32.f32 %0, %1;" : "=f"(r) : "f"(x));
    return r;
}

__device__ __forceinline__ void mma_tf32(float (&c)[4], const uint32_t (&a)[4],
                                         const uint32_t (&b)[2]) {
    asm volatile(
        "mma.sync.aligned.m16n8k8.row.col.f32.tf32.tf32.f32 "
        "{%0,%1,%2,%3}, {%4,%5,%6,%7}, {%8,%9}, {%0,%1,%2,%3};"
        : "+f"(c[0]), "+f"(c[1]), "+f"(c[2]), "+f"(c[3])
        : "r"(a[0]), "r"(a[1]), "r"(a[2]), "r"(a[3]), "r"(b[0]), "r"(b[1]));
}

__device__ __forceinline__ void cp_async16(void* smem, const void* gmem) {
    uint32_t s = (uint32_t)__cvta_generic_to_shared(smem);
    asm volatile("cp.async.cg.shared.global [%0], [%1], 16;" :: "r"(s), "l"(gmem));
}
#define CP_COMMIT() asm volatile("cp.async.commit_group;")
#define CP_WAIT0()  asm volatile("cp.async.wait_group 0;")

// ---------------- pipelined tf32 GEMM core ----------------------------------
// 256 threads = 8 warps (2x4); warp tile 64x32; block tile 128x128; BK=16.
// A: [M][K] row-major (tf32-rounded). B: [K][N] row-major (tf32-rounded).
// Double-buffered smem via cp.async; one __syncthreads per k-iteration.
template <int KDIM>
__device__ __forceinline__ void gemm_tf32(const float* __restrict__ A,
                                          const float* __restrict__ B,
                                          int lda, int ldb,
                                          int m0, int n0,
                                          float (&acc)[4][4][4]) {
    __shared__ float As[2][BM][A_LD];
    __shared__ float Bs[2][BK][B_LD];
    const int tid  = threadIdx.x;
    const int lane = tid & 31;
    const int warp = tid >> 5;
    const int wr   = warp >> 2;   // 0..1 -> m offset 64
    const int wc   = warp & 3;    // 0..3 -> n offset 32
    const int gp   = lane >> 2;   // 0..7
    const int tg   = lane & 3;    // 0..3

    // per-thread cp.async assignments
    const int ar0 = tid >> 2, ac0 = (tid & 3) * 4;            // A chunk 0
    const int ar1 = (tid + 256) >> 2, ac1 = ar0 & 0 ? 0 : ((tid & 3) * 4); // same c
    const int br0 = tid >> 5, bc0 = (tid & 31) * 4;           // B chunk 0
    const int br1 = (tid + 256) >> 5, bc1 = (tid & 31) * 4;   // B chunk 1

    auto issue = [&](int it) {
        const int k0 = it * BK;
        const int s  = it & 1;
        cp_async16(&As[s][ar0][ac0], A + (size_t)(m0 + ar0) * lda + k0 + ac0);
        cp_async16(&As[s][ar1][ac1], A + (size_t)(m0 + ar1) * lda + k0 + ac1);
        cp_async16(&Bs[s][br0][bc0], B + (size_t)(k0 + br0) * ldb + n0 + bc0);
        cp_async16(&Bs[s][br1][bc1], B + (size_t)(k0 + br1) * ldb + n0 + bc1);
        CP_COMMIT();
    };

    constexpr int NIT = KDIM / BK;
    issue(0);
    for (int it = 0; it < NIT; ++it) {
        CP_WAIT0();
        __syncthreads();
        if (it + 1 < NIT) issue(it + 1);
        const int s = it & 1;
        #pragma unroll
        for (int kk = 0; kk < BK; kk += 8) {
            uint32_t a[4][4], b[4][2];
            #pragma unroll
            for (int mi = 0; mi < 4; mi++) {
                const int row = wr * 64 + mi * 16 + gp;
                a[mi][0] = __float_as_uint(As[s][row    ][kk + tg    ]);
                a[mi][1] = __float_as_uint(As[s][row + 8][kk + tg    ]);
                a[mi][2] = __float_as_uint(As[s][row    ][kk + tg + 4]);
                a[mi][3] = __float_as_uint(As[s][row + 8][kk + tg + 4]);
            }
            #pragma unroll
            for (int nj = 0; nj < 4; nj++) {
                const int col = wc * 32 + nj * 8 + gp;
                b[nj][0] = __float_as_uint(Bs[s][kk + tg    ][col]);
                b[nj][1] = __float_as_uint(Bs[s][kk + tg + 4][col]);
            }
            #pragma unroll
            for (int mi = 0; mi < 4; mi++)
                #pragma unroll
                for (int nj = 0; nj < 4; nj++)
                    mma_tf32(acc[mi][nj], a[mi], b[nj]);
        }
        __syncthreads();
    }
}

// Epilogue indices: m = m0 + wr*64 + mi*16 + gp + (e>=2 ? 8 : 0)
//                   n = n0 + wc*32 + nj*8 + 2*tg + (e&1)

// ---------------- prepass: tf32-round an array ------------------------------
__global__ __launch_bounds__(256) void k_round(const float4* __restrict__ src,
                                               float4* __restrict__ dst, int n4) {
    const int i = blockIdx.x * 256 + threadIdx.x;
    if (i < n4) {
        const float4 v = src[i];
        dst[i] = make_float4(to_tf32(v.x), to_tf32(v.y), to_tf32(v.z), to_tf32(v.w));
    }
}

// ---------------- kernel 1: h = silu(X @ Wi + bi), split u/v/q/kT -----------
__global__ __launch_bounds__(256) void k_gemm1(const float* __restrict__ bi,
                                               const float* __restrict__ gamma,
                                               const float* __restrict__ beta) {
    float acc[4][4][4] = {};
    const int m0 = blockIdx.y * BM;
    const int n0 = blockIdx.x * BN;
    gemm_tf32<HIDDEN>(g_hs, g_wi, HIDDEN, N1, m0, n0, acc);

    const int lane = threadIdx.x & 31, warp = threadIdx.x >> 5;
    const int wr = warp >> 2, wc = warp & 3, gp = lane >> 2, tg = lane & 3;

    #pragma unroll
    for (int mi = 0; mi < 4; mi++)
        #pragma unroll
        for (int nj = 0; nj < 4; nj++)
            #pragma unroll
            for (int e = 0; e < 4; e++) {
                const int m = m0 + wr * 64 + mi * 16 + gp + ((e >> 1) << 3);
                const int n = n0 + wc * 32 + nj * 8 + 2 * tg + (e & 1);
                const float x = acc[mi][nj][e] + bi[n];
                const float sv = x / (1.0f + expf(-x));   // silu
                if (n0 < INTER) {
                    g_u[(size_t)m * INTER + n] = sv;                       // raw
                } else if (n0 < 2 * INTER) {
                    g_v[(size_t)m * INTER + (n - INTER)] = to_tf32(sv);
                } else {
                    const int c = n - 2 * INTER;
                    const int b = m >> 11;         // m / SEQ
                    const int s = m & (SEQ - 1);   // m % SEQ
                    g_q[(size_t)m * KEY + c] = to_tf32(sv * gamma[c] + beta[c]);
                    g_kT[((size_t)b * KEY + c) * SEQ + s] =
                        to_tf32(sv * gamma[KEY + c] + beta[KEY + c]);
                }
            }
}

// ---------------- kernel 2: scores = q @ k^T / sqrt(KEY) + mask -------------
__global__ __launch_bounds__(256) void k_scores(const int* __restrict__ mask) {
    const int b = blockIdx.z;
    float acc[4][4][4] = {};
    const int m0 = blockIdx.y * BM;
    const int n0 = blockIdx.x * BN;
    gemm_tf32<KEY>(g_q + (size_t)b * SEQ * KEY,
                   g_kT + (size_t)b * KEY * SEQ,
                   KEY, SEQ, m0, n0, acc);

    float* sc = g_scores + (size_t)b * SEQ * SEQ;
    const float inv = 0.08838834764831845f;  // 1/sqrt(128)
    const int lane = threadIdx.x & 31, warp = threadIdx.x >> 5;
    const int wr = warp >> 2, wc = warp & 3, gp = lane >> 2, tg = lane & 3;

    #pragma unroll
    for (int nj = 0; nj < 4; nj++) {
        const int n = n0 + wc * 32 + nj * 8 + 2 * tg;
        const float am0 = (1.0f - (float)mask[b * SEQ + n    ]) * -1.0e12f;
        const float am1 = (1.0f - (float)mask[b * SEQ + n + 1]) * -1.0e12f;
        #pragma unroll
        for (int mi = 0; mi < 4; mi++) {
            const int m = m0 + wr * 64 + mi * 16 + gp;
            sc[(size_t)m * SEQ + n    ]       = acc[mi][nj][0] * inv + am0;
            sc[(size_t)m * SEQ + n + 1]       = acc[mi][nj][1] * inv + am1;
            sc[(size_t)(m + 8) * SEQ + n    ] = acc[mi][nj][2] * inv + am0;
            sc[(size_t)(m + 8) * SEQ + n + 1] = acc[mi][nj][3] * inv + am1;
        }
    }
}

// ---------------- kernel 3: length-scaled softmax (writes tf32 attn) --------
__global__ __launch_bounds__(256) void k_softmax() {
    float* sc = g_scores + (size_t)blockIdx.x * SEQ;
    const int tid = threadIdx.x;
    __shared__ float red[256];

    float vals[8];
    int cnt = 0;
    #pragma unroll
    for (int t = 0; t < 8; t++) {
        vals[t] = sc[tid + t * 256];
        cnt += (vals[t] > -1.0e11f) ? 1 : 0;
    }
    red[tid] = (float)cnt;
    __syncthreads();
    for (int s = 128; s > 0; s >>= 1) {
        if (tid < s) red[tid] += red[tid + s];
        __syncthreads();
    }
    const float l = fmaxf(red[0], 1.0f);
    const float scale = logf(l) * (1.0f / logf(512.0f));
    __syncthreads();

    float mx = -INFINITY;
    #pragma unroll
    for (int t = 0; t < 8; t++) {
        vals[t] *= scale;
        mx = fmaxf(mx, vals[t]);
    }
    red[tid] = mx;
    __syncthreads();
    for (int s = 128; s > 0; s >>= 1) {
        if (tid < s) red[tid] = fmaxf(red[tid], red[tid + s]);
        __syncthreads();
    }
    mx = red[0];
    __syncthreads();

    float sum = 0.0f;
    #pragma unroll
    for (int t = 0; t < 8; t++) {
        vals[t] = expf(vals[t] - mx);
        sum += vals[t];
    }
    red[tid] = sum;
    __syncthreads();
    for (int s = 128; s > 0; s >>= 1) {
        if (tid < s) red[tid] += red[tid + s];
        __syncthreads();
    }
    const float invsum = 1.0f / red[0];
    #pragma unroll
    for (int t = 0; t < 8; t++)
        sc[tid + t * 256] = to_tf32(vals[t] * invsum);
}

// ---------------- kernel 4: g = tf32(u * (attn @ v)), in place into g_u -----
__global__ __launch_bounds__(256) void k_ctx() {
    const int b = blockIdx.z;
    float acc[4][4][4] = {};
    const int m0 = blockIdx.y * BM;
    const int n0 = blockIdx.x * BN;
    gemm_tf32<SEQ>(g_scores + (size_t)b * SEQ * SEQ,
                   g_v + (size_t)b * SEQ * INTER,
                   SEQ, INTER, m0, n0, acc);

    const int lane = threadIdx.x & 31, warp = threadIdx.x >> 5;
    const int wr = warp >> 2, wc = warp & 3, gp = lane >> 2, tg = lane & 3;

    #pragma unroll
    for (int mi = 0; mi < 4; mi++)
        #pragma unroll
        for (int nj = 0; nj < 4; nj++)
            #pragma unroll
            for (int e = 0; e < 4; e++) {
                const int m = m0 + wr * 64 + mi * 16 + gp + ((e >> 1) << 3);
                const int n = n0 + wc * 32 + nj * 8 + 2 * tg + (e & 1);
                const size_t idx = ((size_t)b * SEQ + m) * INTER + n;
                g_u[idx] = to_tf32(g_u[idx] * acc[mi][nj][e]);
            }
}

// ---------------- kernel 5: out = g @ Wo + bo -------------------------------
__global__ __launch_bounds__(256) void k_out(const float* __restrict__ bo,
                                             float* __restrict__ out) {
    float acc[4][4][4] = {};
    const int m0 = blockIdx.y * BM;
    const int n0 = blockIdx.x * BN;
    gemm_tf32<INTER>(g_u, g_wo, INTER, HIDDEN, m0, n0, acc);

    const int lane = threadIdx.x & 31, warp = threadIdx.x >> 5;
    const int wr = warp >> 2, wc = warp & 3, gp = lane >> 2, tg = lane & 3;

    #pragma unroll
    for (int mi = 0; mi < 4; mi++)
        #pragma unroll
        for (int nj = 0; nj < 4; nj++)
            #pragma unroll
            for (int e = 0; e < 4; e++) {
                const int m = m0 + wr * 64 + mi * 16 + gp + ((e >> 1) << 3);
                const int n = n0 + wc * 32 + nj * 8 + 2 * tg + (e & 1);
                out[(size_t)m * HIDDEN + n] = acc[mi][nj][e] + bo[n];
            }
}

// ---------------- launch -----------------------------------------------------
extern "C" void kernel_launch(void* const* d_in, const int* in_sizes, int n_in,
                              void* d_out, int out_size) {
    const float* hs    = (const float*)d_in[0];
    const int*   mask  = (const int*)  d_in[1];
    // d_in[2] = position_ids (unused)
    const float* Wi    = (const float*)d_in[3];
    const float* bi    = (const float*)d_in[4];
    const float* gamma = (const float*)d_in[5];
    const float* beta  = (const float*)d_in[6];
    const float* Wo    = (const float*)d_in[7];
    const float* bo    = (const float*)d_in[8];
    float* out = (float*)d_out;

    float *p_hs, *p_wi, *p_wo;
    cudaGetSymbolAddress((void**)&p_hs, g_hs);
    cudaGetSymbolAddress((void**)&p_wi, g_wi);
    cudaGetSymbolAddress((void**)&p_wo, g_wo);

    dim3 blk(256);
    {
        const int n4 = M_TOT * HIDDEN / 4;
        k_round<<<(n4 + 255) / 256, blk>>>((const float4*)hs, (float4*)p_hs, n4);
    }
    {
        const int n4 = HIDDEN * N1 / 4;
        k_round<<<(n4 + 255) / 256, blk>>>((const float4*)Wi, (float4*)p_wi, n4);
    }
    {
        const int n4 = INTER * HIDDEN / 4;
        k_round<<<(n4 + 255) / 256, blk>>>((const float4*)Wo, (float4*)p_wo, n4);
    }

    k_gemm1  <<<dim3(N1 / BN, M_TOT / BM), blk>>>(bi, gamma, beta);
    k_scores <<<dim3(SEQ / BN, SEQ / BM, BDIM), blk>>>(mask);
    k_softmax<<<dim3(M_TOT), blk>>>();
    k_ctx    <<<dim3(INTER / BN, SEQ / BM, BDIM), blk>>>();
    k_out    <<<dim3(HIDDEN / BN, M_TOT / BM), blk>>>(bo, out);
}

// round 4
// speedup vs baseline: 3.9796x; 1.1344x over previous
#include <cuda_runtime.h>
#include <math.h>
#include <stdint.h>

#define HIDDEN 768
#define KEY    128
#define INTER  1536
#define BDIM   4
#define SEQ    2048
#define M_TOT  (BDIM*SEQ)        // 8192
#define N1     (2*INTER+KEY)     // 3200

#define BM 128
#define BN 128
#define BK 32
#define STAGES 3
#define A_LD 36      // As[r][c]: bank (4r+c)%32, lanes 4gp+tg distinct -> conflict-free
#define B_LD 136     // Bs[k][n]: bank (8k+n)%32, lanes 8tg+gp distinct -> conflict-free
#define A_STAGE (BM * A_LD)
#define B_STAGE (BK * B_LD)
#define SMEM_BYTES ((STAGES * (A_STAGE + B_STAGE)) * 4)   // 107,520 B

// ---------------- scratch (device globals; no allocation allowed) ----------
__device__ float g_u[(size_t)M_TOT * INTER];           // u (raw), then tf32(u*ctx)
__device__ float g_v[(size_t)M_TOT * INTER];           // tf32-rounded v
__device__ float g_q[(size_t)M_TOT * KEY];             // tf32-rounded q
__device__ float g_kT[(size_t)BDIM * KEY * SEQ];       // tf32-rounded k, transposed
__device__ float g_scores[(size_t)BDIM * SEQ * SEQ];   // scores -> tf32 attn in place
__device__ float g_hs[(size_t)M_TOT * HIDDEN];         // tf32-rounded hidden_states
__device__ float g_wi[(size_t)HIDDEN * N1];            // tf32-rounded Wi
__device__ float g_wo[(size_t)INTER * HIDDEN];         // tf32-rounded Wo

// ---------------- helpers ---------------------------------------------------
__device__ __forceinline__ float to_tf32(float x) {
    float r;
    asm("cvt.rna.tf32.f32 %0, %1;" : "=f"(r) : "f"(x));
    return r;
}

__device__ __forceinline__ void mma_tf32(float (&c)[4], const uint32_t (&a)[4],
                                         const uint32_t (&b)[2]) {
    asm volatile(
        "mma.sync.aligned.m16n8k8.row.col.f32.tf32.tf32.f32 "
        "{%0,%1,%2,%3}, {%4,%5,%6,%7}, {%8,%9}, {%0,%1,%2,%3};"
        : "+f"(c[0]), "+f"(c[1]), "+f"(c[2]), "+f"(c[3])
        : "r"(a[0]), "r"(a[1]), "r"(a[2]), "r"(a[3]), "r"(b[0]), "r"(b[1]));
}

__device__ __forceinline__ void cp_async16(float* smem, const float* gmem) {
    uint32_t s = (uint32_t)__cvta_generic_to_shared(smem);
    asm volatile("cp.async.cg.shared.global [%0], [%1], 16;" :: "r"(s), "l"(gmem));
}
#define CP_COMMIT() asm volatile("cp.async.commit_group;")
#define CP_WAIT1()  asm volatile("cp.async.wait_group 1;")

// ---------------- 3-stage pipelined tf32 GEMM core ---------------------------
// 256 threads = 8 warps (2x4); warp tile 64x32; block tile 128x128; BK=32.
// A: [M][K] row-major (tf32-rounded). B: [K][N] row-major (tf32-rounded).
// Dynamic smem: STAGES x (A tile + B tile). One __syncthreads per k-iter.
template <int KDIM>
__device__ __forceinline__ void gemm_tf32(const float* __restrict__ A,
                                          const float* __restrict__ B,
                                          int lda, int ldb,
                                          int m0, int n0,
                                          float (&acc)[4][4][4]) {
    extern __shared__ float sm[];
    float* Abuf = sm;                        // STAGES * A_STAGE
    float* Bbuf = sm + STAGES * A_STAGE;     // STAGES * B_STAGE

    const int tid  = threadIdx.x;
    const int lane = tid & 31;
    const int warp = tid >> 5;
    const int wr   = warp >> 2;   // 0..1 -> m offset 64
    const int wc   = warp & 3;    // 0..3 -> n offset 32
    const int gp   = lane >> 2;   // 0..7
    const int tg   = lane & 3;    // 0..3

    constexpr int NIT = KDIM / BK;

    // issue stage for iteration `it` into buffer it%STAGES; ALWAYS commits.
    auto issue = [&](int it) {
        if (it < NIT) {
            const int k0 = it * BK;
            float* As = Abuf + (it % STAGES) * A_STAGE;
            float* Bs = Bbuf + (it % STAGES) * B_STAGE;
            #pragma unroll
            for (int t = 0; t < 4; t++) {
                const int id = tid + t * 256;       // 0..1023
                const int ar = id >> 3;             // 0..127
                const int ac = (id & 7) * 4;        // 0..28
                cp_async16(As + ar * A_LD + ac,
                           A + (size_t)(m0 + ar) * lda + k0 + ac);
            }
            #pragma unroll
            for (int t = 0; t < 4; t++) {
                const int id = tid + t * 256;
                const int br = id >> 5;             // 0..31
                const int bc = (id & 31) * 4;       // 0..124
                cp_async16(Bs + br * B_LD + bc,
                           B + (size_t)(k0 + br) * ldb + n0 + bc);
            }
        }
        CP_COMMIT();
    };

    issue(0);
    issue(1);

    for (int it = 0; it < NIT; ++it) {
        CP_WAIT1();          // all but newest group done -> stage `it` ready
        __syncthreads();     // also guards reuse of buffer (it+2)%3 below
        issue(it + 2);

        const float* As = Abuf + (it % STAGES) * A_STAGE;
        const float* Bs = Bbuf + (it % STAGES) * B_STAGE;

        #pragma unroll
        for (int kk = 0; kk < BK; kk += 8) {
            uint32_t a[4][4], b[4][2];
            #pragma unroll
            for (int mi = 0; mi < 4; mi++) {
                const int row = wr * 64 + mi * 16 + gp;
                a[mi][0] = __float_as_uint(As[(row    ) * A_LD + kk + tg    ]);
                a[mi][1] = __float_as_uint(As[(row + 8) * A_LD + kk + tg    ]);
                a[mi][2] = __float_as_uint(As[(row    ) * A_LD + kk + tg + 4]);
                a[mi][3] = __float_as_uint(As[(row + 8) * A_LD + kk + tg + 4]);
            }
            #pragma unroll
            for (int nj = 0; nj < 4; nj++) {
                const int col = wc * 32 + nj * 8 + gp;
                b[nj][0] = __float_as_uint(Bs[(kk + tg    ) * B_LD + col]);
                b[nj][1] = __float_as_uint(Bs[(kk + tg + 4) * B_LD + col]);
            }
            #pragma unroll
            for (int mi = 0; mi < 4; mi++)
                #pragma unroll
                for (int nj = 0; nj < 4; nj++)
                    mma_tf32(acc[mi][nj], a[mi], b[nj]);
        }
    }
}

// Epilogue indices: m = m0 + wr*64 + mi*16 + gp + (e>=2 ? 8 : 0)
//                   n = n0 + wc*32 + nj*8 + 2*tg + (e&1)

// ---------------- prepass: tf32-round an array -------------------------------
__global__ __launch_bounds__(256) void k_round(const float4* __restrict__ src,
                                               float4* __restrict__ dst, int n4) {
    const int i = blockIdx.x * 256 + threadIdx.x;
    if (i < n4) {
        const float4 v = src[i];
        dst[i] = make_float4(to_tf32(v.x), to_tf32(v.y), to_tf32(v.z), to_tf32(v.w));
    }
}

// ---------------- kernel 1: h = silu(X @ Wi + bi), split u/v/q/kT ------------
__global__ __launch_bounds__(256) void k_gemm1(const float* __restrict__ bi,
                                               const float* __restrict__ gamma,
                                               const float* __restrict__ beta) {
    float acc[4][4][4] = {};
    const int m0 = blockIdx.y * BM;
    const int n0 = blockIdx.x * BN;
    gemm_tf32<HIDDEN>(g_hs, g_wi, HIDDEN, N1, m0, n0, acc);

    const int lane = threadIdx.x & 31, warp = threadIdx.x >> 5;
    const int wr = warp >> 2, wc = warp & 3, gp = lane >> 2, tg = lane & 3;

    #pragma unroll
    for (int mi = 0; mi < 4; mi++)
        #pragma unroll
        for (int nj = 0; nj < 4; nj++)
            #pragma unroll
            for (int e = 0; e < 4; e++) {
                const int m = m0 + wr * 64 + mi * 16 + gp + ((e >> 1) << 3);
                const int n = n0 + wc * 32 + nj * 8 + 2 * tg + (e & 1);
                const float x = acc[mi][nj][e] + bi[n];
                const float sv = x / (1.0f + expf(-x));   // silu
                if (n0 < INTER) {
                    g_u[(size_t)m * INTER + n] = sv;                       // raw
                } else if (n0 < 2 * INTER) {
                    g_v[(size_t)m * INTER + (n - INTER)] = to_tf32(sv);
                } else {
                    const int c = n - 2 * INTER;
                    const int b = m >> 11;         // m / SEQ
                    const int s = m & (SEQ - 1);   // m % SEQ
                    g_q[(size_t)m * KEY + c] = to_tf32(sv * gamma[c] + beta[c]);
                    g_kT[((size_t)b * KEY + c) * SEQ + s] =
                        to_tf32(sv * gamma[KEY + c] + beta[KEY + c]);
                }
            }
}

// ---------------- kernel 2: scores = q @ k^T / sqrt(KEY) + mask --------------
__global__ __launch_bounds__(256) void k_scores(const int* __restrict__ mask) {
    const int b = blockIdx.z;
    float acc[4][4][4] = {};
    const int m0 = blockIdx.y * BM;
    const int n0 = blockIdx.x * BN;
    gemm_tf32<KEY>(g_q + (size_t)b * SEQ * KEY,
                   g_kT + (size_t)b * KEY * SEQ,
                   KEY, SEQ, m0, n0, acc);

    float* sc = g_scores + (size_t)b * SEQ * SEQ;
    const float inv = 0.08838834764831845f;  // 1/sqrt(128)
    const int lane = threadIdx.x & 31, warp = threadIdx.x >> 5;
    const int wr = warp >> 2, wc = warp & 3, gp = lane >> 2, tg = lane & 3;

    #pragma unroll
    for (int nj = 0; nj < 4; nj++) {
        const int n = n0 + wc * 32 + nj * 8 + 2 * tg;
        const float am0 = (1.0f - (float)mask[b * SEQ + n    ]) * -1.0e12f;
        const float am1 = (1.0f - (float)mask[b * SEQ + n + 1]) * -1.0e12f;
        #pragma unroll
        for (int mi = 0; mi < 4; mi++) {
            const int m = m0 + wr * 64 + mi * 16 + gp;
            sc[(size_t)m * SEQ + n    ]       = acc[mi][nj][0] * inv + am0;
            sc[(size_t)m * SEQ + n + 1]       = acc[mi][nj][1] * inv + am1;
            sc[(size_t)(m + 8) * SEQ + n    ] = acc[mi][nj][2] * inv + am0;
            sc[(size_t)(m + 8) * SEQ + n + 1] = acc[mi][nj][3] * inv + am1;
        }
    }
}

// ---------------- kernel 3: length-scaled softmax (writes tf32 attn) ---------
__global__ __launch_bounds__(256) void k_softmax() {
    float* sc = g_scores + (size_t)blockIdx.x * SEQ;
    const int tid = threadIdx.x;
    __shared__ float red[256];

    float vals[8];
    int cnt = 0;
    #pragma unroll
    for (int t = 0; t < 8; t++) {
        vals[t] = sc[tid + t * 256];
        cnt += (vals[t] > -1.0e11f) ? 1 : 0;
    }
    red[tid] = (float)cnt;
    __syncthreads();
    for (int s = 128; s > 0; s >>= 1) {
        if (tid < s) red[tid] += red[tid + s];
        __syncthreads();
    }
    const float l = fmaxf(red[0], 1.0f);
    const float scale = logf(l) * (1.0f / logf(512.0f));
    __syncthreads();

    float mx = -INFINITY;
    #pragma unroll
    for (int t = 0; t < 8; t++) {
        vals[t] *= scale;
        mx = fmaxf(mx, vals[t]);
    }
    red[tid] = mx;
    __syncthreads();
    for (int s = 128; s > 0; s >>= 1) {
        if (tid < s) red[tid] = fmaxf(red[tid], red[tid + s]);
        __syncthreads();
    }
    mx = red[0];
    __syncthreads();

    float sum = 0.0f;
    #pragma unroll
    for (int t = 0; t < 8; t++) {
        vals[t] = expf(vals[t] - mx);
        sum += vals[t];
    }
    red[tid] = sum;
    __syncthreads();
    for (int s = 128; s > 0; s >>= 1) {
        if (tid < s) red[tid] += red[tid + s];
        __syncthreads();
    }
    const float invsum = 1.0f / red[0];
    #pragma unroll
    for (int t = 0; t < 8; t++)
        sc[tid + t * 256] = to_tf32(vals[t] * invsum);
}

// ---------------- kernel 4: g = tf32(u * (attn @ v)), in place into g_u ------
__global__ __launch_bounds__(256) void k_ctx() {
    const int b = blockIdx.z;
    float acc[4][4][4] = {};
    const int m0 = blockIdx.y * BM;
    const int n0 = blockIdx.x * BN;
    gemm_tf32<SEQ>(g_scores + (size_t)b * SEQ * SEQ,
                   g_v + (size_t)b * SEQ * INTER,
                   SEQ, INTER, m0, n0, acc);

    const int lane = threadIdx.x & 31, warp = threadIdx.x >> 5;
    const int wr = warp >> 2, wc = warp & 3, gp = lane >> 2, tg = lane & 3;

    #pragma unroll
    for (int mi = 0; mi < 4; mi++)
        #pragma unroll
        for (int nj = 0; nj < 4; nj++)
            #pragma unroll
            for (int e = 0; e < 4; e++) {
                const int m = m0 + wr * 64 + mi * 16 + gp + ((e >> 1) << 3);
                const int n = n0 + wc * 32 + nj * 8 + 2 * tg + (e & 1);
                const size_t idx = ((size_t)b * SEQ + m) * INTER + n;
                g_u[idx] = to_tf32(g_u[idx] * acc[mi][nj][e]);
            }
}

// ---------------- kernel 5: out = g @ Wo + bo --------------------------------
__global__ __launch_bounds__(256) void k_out(const float* __restrict__ bo,
                                             float* __restrict__ out) {
    float acc[4][4][4] = {};
    const int m0 = blockIdx.y * BM;
    const int n0 = blockIdx.x * BN;
    gemm_tf32<INTER>(g_u, g_wo, INTER, HIDDEN, m0, n0, acc);

    const int lane = threadIdx.x & 31, warp = threadIdx.x >> 5;
    const int wr = warp >> 2, wc = warp & 3, gp = lane >> 2, tg = lane & 3;

    #pragma unroll
    for (int mi = 0; mi < 4; mi++)
        #pragma unroll
        for (int nj = 0; nj < 4; nj++)
            #pragma unroll
            for (int e = 0; e < 4; e++) {
                const int m = m0 + wr * 64 + mi * 16 + gp + ((e >> 1) << 3);
                const int n = n0 + wc * 32 + nj * 8 + 2 * tg + (e & 1);
                out[(size_t)m * HIDDEN + n] = acc[mi][nj][e] + bo[n];
            }
}

// ---------------- launch ------------------------------------------------------
extern "C" void kernel_launch(void* const* d_in, const int* in_sizes, int n_in,
                              void* d_out, int out_size) {
    const float* hs    = (const float*)d_in[0];
    const int*   mask  = (const int*)  d_in[1];
    // d_in[2] = position_ids (unused)
    const float* Wi    = (const float*)d_in[3];
    const float* bi    = (const float*)d_in[4];
    const float* gamma = (const float*)d_in[5];
    const float* beta  = (const float*)d_in[6];
    const float* Wo    = (const float*)d_in[7];
    const float* bo    = (const float*)d_in[8];
    float* out = (float*)d_out;

    float *p_hs, *p_wi, *p_wo;
    cudaGetSymbolAddress((void**)&p_hs, g_hs);
    cudaGetSymbolAddress((void**)&p_wi, g_wi);
    cudaGetSymbolAddress((void**)&p_wo, g_wo);

    cudaFuncSetAttribute(k_gemm1,  cudaFuncAttributeMaxDynamicSharedMemorySize, SMEM_BYTES);
    cudaFuncSetAttribute(k_scores, cudaFuncAttributeMaxDynamicSharedMemorySize, SMEM_BYTES);
    cudaFuncSetAttribute(k_ctx,    cudaFuncAttributeMaxDynamicSharedMemorySize, SMEM_BYTES);
    cudaFuncSetAttribute(k_out,    cudaFuncAttributeMaxDynamicSharedMemorySize, SMEM_BYTES);

    dim3 blk(256);
    {
        const int n4 = M_TOT * HIDDEN / 4;
        k_round<<<(n4 + 255) / 256, blk>>>((const float4*)hs, (float4*)p_hs, n4);
    }
    {
        const int n4 = HIDDEN * N1 / 4;
        k_round<<<(n4 + 255) / 256, blk>>>((const float4*)Wi, (float4*)p_wi, n4);
    }
    {
        const int n4 = INTER * HIDDEN / 4;
        k_round<<<(n4 + 255) / 256, blk>>>((const float4*)Wo, (float4*)p_wo, n4);
    }

    k_gemm1  <<<dim3(N1 / BN, M_TOT / BM), blk, SMEM_BYTES>>>(bi, gamma, beta);
    k_scores <<<dim3(SEQ / BN, SEQ / BM, BDIM), blk, SMEM_BYTES>>>(mask);
    k_softmax<<<dim3(M_TOT), blk>>>();
    k_ctx    <<<dim3(INTER / BN, SEQ / BM, BDIM), blk, SMEM_BYTES>>>();
    k_out    <<<dim3(HIDDEN / BN, M_TOT / BM), blk, SMEM_BYTES>>>(bo, out);
}